// round 13
// baseline (speedup 1.0000x reference)
#include <cuda_runtime.h>
#include <cuda_fp16.h>
#include <math.h>
#include <stdint.h>

#define Bc 2
#define Sc 2048
#define Ec 1024
#define Hc 16
#define Dc 64
#define Fc 4096
#define Mc (Bc*Sc)          // 4096 rows
#define MB (1024*1024)

// ---------------- scratch (no cudaMalloc allowed) ----------------
__device__ __half g_n  [Mc*Ec];     // LN1 out (half, GEMM A)
__device__ __half g_q  [Mc*Ec];     // Q half [B,H,S,D], pre-scaled by 0.125*log2e
__device__ __half g_k  [Mc*Ec];     // K half [B,H,S,D]
__device__ __half g_v  [Mc*Ec];     // V half [B,H,D,S]  (TRANSPOSED)
__device__ __half g_ctx[Mc*Ec];     // attn out (half, GEMM A)
__device__ float  g_res[Mc*Ec];
__device__ float  g_x2 [Mc*Ec];     // LN2 out fp32 (residual)
__device__ __half g_x2h[Mc*Ec];     // LN2 out half (GEMM A)
__device__ __half g_f1 [Mc*Fc];     // GELU out (half, GEMM A)
// packed fp16 weights, BLOCKED: [N/128][K/32][128 n][16 words], 8KB blocks
__device__ uint32_t g_wp[6*MB];
__device__ float  g_bqkv[3072];     // concat bias

// packed-weight word offsets
#define WP_QKV 0
#define WP_O   (3*MB/2)
#define WP_W1  (2*MB)
#define WP_W2  (4*MB)
#define WP_TOT (6*MB)

#define QSCALE 0.1803368801111729f   // 0.125 * log2(e)

// ---------------- helpers ----------------
__device__ __forceinline__ uint32_t packh2(float lo, float hi) {
    __half2 h = __floats2half2_rn(lo, hi);
    return *(uint32_t*)&h;
}

__device__ __forceinline__ void mma16(float* c, const uint32_t* a, const uint32_t* b) {
    asm volatile(
        "mma.sync.aligned.m16n8k16.row.col.f32.f16.f16.f32 "
        "{%0,%1,%2,%3}, {%4,%5,%6,%7}, {%8,%9}, {%0,%1,%2,%3};\n"
        : "+f"(c[0]), "+f"(c[1]), "+f"(c[2]), "+f"(c[3])
        : "r"(a[0]), "r"(a[1]), "r"(a[2]), "r"(a[3]),
          "r"(b[0]), "r"(b[1]));
}

__device__ __forceinline__ void ldsm4(uint32_t& r0, uint32_t& r1, uint32_t& r2, uint32_t& r3,
                                      uint32_t addr) {
    asm volatile("ldmatrix.sync.aligned.m8n8.x4.shared.b16 {%0,%1,%2,%3}, [%4];"
        : "=r"(r0), "=r"(r1), "=r"(r2), "=r"(r3) : "r"(addr));
}

__device__ __forceinline__ void cp16(uint32_t dst, const void* src) {
    asm volatile("cp.async.cg.shared.global [%0], [%1], 16;" :: "r"(dst), "l"(src));
}
#define CP_COMMIT() asm volatile("cp.async.commit_group;")
#define CP_WAIT0()  asm volatile("cp.async.wait_group 0;")
#define CP_WAIT1()  asm volatile("cp.async.wait_group 1;")

// ---------------- weight convert+pack: coalesced tile transpose ----------------
// One CTA per 8KB output block [128 n][16 words]. Reads 32x128 fp32 source tile
// with coalesced float4 rows into smem, emits coalesced uint4 writes.
#define CVT_BLOCKS 3840   // 1536 QKV + 256 Wo + 1024 W1 + 1024 W2

__global__ void __launch_bounds__(256) convert_all(const float* __restrict__ Wq,
                                                   const float* __restrict__ Wk,
                                                   const float* __restrict__ Wv,
                                                   const float* __restrict__ Wo,
                                                   const float* __restrict__ W1,
                                                   const float* __restrict__ W2,
                                                   const float* __restrict__ bq,
                                                   const float* __restrict__ bk,
                                                   const float* __restrict__ bv,
                                                   uint32_t* __restrict__ wp,
                                                   float* __restrict__ bqkv) {
    __shared__ float s[32][133];
    int b = blockIdx.x;
    int t = threadIdx.x;
    if (b < CVT_BLOCKS) {
        const float* W;
        long base, Nsrc;
        int lb, ntile, kt, qkv = 0;
        if (b < 1536)      { base = WP_QKV; lb = b;        ntile = lb >> 5; kt = lb & 31;  Nsrc = 1024; qkv = 1; W = nullptr; }
        else if (b < 1792) { base = WP_O;   lb = b - 1536; ntile = lb >> 5; kt = lb & 31;  Nsrc = 1024; W = Wo; }
        else if (b < 2816) { base = WP_W1;  lb = b - 1792; ntile = lb >> 5; kt = lb & 31;  Nsrc = 4096; W = W1; }
        else               { base = WP_W2;  lb = b - 2816; ntile = lb >> 7; kt = lb & 127; Nsrc = 1024; W = W2; }
        long n0 = (long)ntile * 128;
        if (qkv) {
            int mat = (int)(n0 >> 10);
            W = (mat == 0) ? Wq : (mat == 1) ? Wk : Wv;
            n0 &= 1023;
        }
        int k0 = kt * 32;
        // coalesced read: 32 rows x 128 floats
        #pragma unroll
        for (int i = 0; i < 4; i++) {
            int idx = t + i * 256;
            int r = idx >> 5, c4 = (idx & 31) * 4;
            float4 f = *(const float4*)(W + (size_t)(k0 + r) * Nsrc + n0 + c4);
            s[r][c4 + 0] = f.x; s[r][c4 + 1] = f.y;
            s[r][c4 + 2] = f.z; s[r][c4 + 3] = f.w;
        }
        __syncthreads();
        // coalesced write: 512 uint4 per block
        long blkoff = base + (long)lb * 2048;
        #pragma unroll
        for (int i = 0; i < 2; i++) {
            int u = t + i * 256;
            int n_in = u >> 2, w4 = (u & 3) * 4;
            uint4 wv;
            uint32_t* wr = (uint32_t*)&wv;
            #pragma unroll
            for (int j = 0; j < 4; j++) {
                int wdx = w4 + j;
                wr[j] = packh2(s[2 * wdx][n_in], s[2 * wdx + 1][n_in]);
            }
            *(uint4*)(wp + blkoff + n_in * 16 + w4) = wv;
        }
    } else {
        int j4 = (b - CVT_BLOCKS) * 1024 + t * 4;
        if (j4 < 3072) {
            int mat = j4 >> 10;
            const float* B = (mat == 0) ? bq : (mat == 1) ? bk : bv;
            *(float4*)(bqkv + j4) = *(const float4*)(B + (j4 & 1023));
        }
    }
}

// ---------------- LayerNorm: optional fp32 / half outputs ----------------
template<bool WF, bool WH>
__global__ void __launch_bounds__(256) ln_kernel(const float* __restrict__ x,
                                                 const float* __restrict__ g,
                                                 const float* __restrict__ b,
                                                 float* __restrict__ out_f,
                                                 __half* __restrict__ out_h) {
    int row = blockIdx.x;
    int tid = threadIdx.x;
    const float4* xr = (const float4*)(x + (size_t)row * Ec);
    float4 xv = xr[tid];
    float s  = xv.x + xv.y + xv.z + xv.w;
    float sq = xv.x*xv.x + xv.y*xv.y + xv.z*xv.z + xv.w*xv.w;
    #pragma unroll
    for (int o = 16; o; o >>= 1) {
        s  += __shfl_xor_sync(0xffffffffu, s,  o);
        sq += __shfl_xor_sync(0xffffffffu, sq, o);
    }
    __shared__ float ws[8], wq[8];
    __shared__ float s_mu, s_rstd;
    int lane = tid & 31, wid = tid >> 5;
    if (lane == 0) { ws[wid] = s; wq[wid] = sq; }
    __syncthreads();
    if (tid == 0) {
        float S = 0.f, Q = 0.f;
        #pragma unroll
        for (int i = 0; i < 8; i++) { S += ws[i]; Q += wq[i]; }
        float mu  = S * (1.0f / Ec);
        float var = Q * (1.0f / Ec) - mu * mu;
        s_mu = mu;
        s_rstd = rsqrtf(var + 1e-5f);
    }
    __syncthreads();
    float mu = s_mu, rstd = s_rstd;
    float4 gv = ((const float4*)g)[tid];
    float4 bv = ((const float4*)b)[tid];
    float4 ov;
    ov.x = (xv.x - mu) * rstd * gv.x + bv.x;
    ov.y = (xv.y - mu) * rstd * gv.y + bv.y;
    ov.z = (xv.z - mu) * rstd * gv.z + bv.z;
    ov.w = (xv.w - mu) * rstd * gv.w + bv.w;
    if (WF) ((float4*)(out_f + (size_t)row * Ec))[tid] = ov;
    if (WH) {
        uint2 hw;
        hw.x = packh2(ov.x, ov.y);
        hw.y = packh2(ov.z, ov.w);
        *(uint2*)(out_h + (size_t)row * Ec + tid * 4) = hw;
    }
}

// ---------------- fp16 TC GEMM: 128x128x32, 8 warps, 3-stage cp.async, full ldmatrix ----------------
enum { EP_PLAIN = 0, EP_HEADS = 1, EP_RES = 2, EP_GELU = 3 };

#define BM 128
#define BN 128
#define BKH 32                       // k-tile in halves
#define LDA2 20                      // As row stride in words (m rows)
#define LDBW2 20                     // Bs row stride in words (n rows)
#define STG_A2 (BM * LDA2)           // 2560 words
#define STG_B2 (BN * LDBW2)          // 2560 words
#define STG2   (STG_A2 + STG_B2)     // 5120 words
#define NSTAGE 3
#define TG_SMEM (NSTAGE * STG2 * 4)  // 61440 bytes

// A: __half [M][K]; Wp: blocked [N/128][K/32][128][16] words
template<int EP>
__global__ void __launch_bounds__(256, 2) hgemm(const __half* __restrict__ A,
                                                const uint32_t* __restrict__ Wp,
                                                const float* __restrict__ bias,
                                                const float* __restrict__ res,
                                                float* __restrict__ C,
                                                __half* __restrict__ Ch,
                                                __half* __restrict__ Hq,
                                                __half* __restrict__ Hk,
                                                __half* __restrict__ Hv,
                                                int M, int N, int K) {
    extern __shared__ uint32_t sh[];
    uint32_t smem_u = (uint32_t)__cvta_generic_to_shared(sh);

    int tid  = threadIdx.x;
    int lane = tid & 31;
    int w    = tid >> 5;
    int wm   = (w & 3) * 32;
    int wn   = (w >> 2) * 64;
    int row0 = blockIdx.y * BM;
    int col0 = blockIdx.x * BN;

    const __half* Ab = A + (size_t)row0 * K;
    const uint32_t* Wb = Wp + (size_t)(col0 >> 7) * (size_t)(K >> 5) * 2048;

    auto issue = [&](int kt, int s) {
        uint32_t sa = smem_u + (uint32_t)(s * STG2) * 4u;
        uint32_t sb = sa + (uint32_t)STG_A2 * 4u;
        int k0 = kt * BKH;                        // halves (A)
        const uint32_t* Bblk = Wb + (size_t)kt * 2048;
        #pragma unroll
        for (int j = 0; j < 2; j++) {
            int idx = tid + j * 256;
            int r  = idx >> 2, wo = (idx & 3) * 4;
            cp16(sa + (uint32_t)(r * LDA2 + wo) * 4u, Ab + (size_t)r * K + k0 + wo * 2);
            cp16(sb + (uint32_t)(r * LDBW2 + wo) * 4u, Bblk + (size_t)idx * 4);
        }
        CP_COMMIT();
    };

    float acc[2][8][4];
    #pragma unroll
    for (int mi = 0; mi < 2; mi++)
        #pragma unroll
        for (int ni = 0; ni < 8; ni++)
            #pragma unroll
            for (int q = 0; q < 4; q++) acc[mi][ni][q] = 0.f;

    int nk = K / BKH;
    issue(0, 0);
    issue(1, 1);

    int r_ = lane >> 2, c_ = lane & 3;
    int lrow = (lane & 7) + ((lane >> 3) & 1) * 8;   // ldmatrix A row pattern
    int lcol = (lane >> 4) * 4;                      // ldmatrix A col offset (words)
    int brow = (lane >> 3) * 8 + (lane & 7);         // ldmatrix B row pattern

    int st = 0;
    for (int kt = 0; kt < nk; kt++) {
        if (kt + 1 < nk) { CP_WAIT1(); } else { CP_WAIT0(); }
        __syncthreads();
        if (kt + 2 < nk) {
            int s2 = st + 2; if (s2 >= NSTAGE) s2 -= NSTAGE;
            issue(kt + 2, s2);
        }

        uint32_t sa_u = smem_u + (uint32_t)(st * STG2) * 4u;
        uint32_t sb_u = sa_u + (uint32_t)STG_A2 * 4u;

        #pragma unroll
        for (int ks = 0; ks < 2; ks++) {
            int kb2 = ks * 8;
            uint32_t af[2][4], bf[8][2];
            #pragma unroll
            for (int mi = 0; mi < 2; mi++) {
                int row = wm + mi * 16 + lrow;
                ldsm4(af[mi][0], af[mi][1], af[mi][2], af[mi][3],
                      sa_u + (uint32_t)(row * LDA2 + kb2 + lcol) * 4u);
            }
            #pragma unroll
            for (int p = 0; p < 2; p++) {
                int row = wn + p * 32 + brow;
                ldsm4(bf[p*4+0][0], bf[p*4+1][0], bf[p*4+2][0], bf[p*4+3][0],
                      sb_u + (uint32_t)(row * LDBW2 + kb2) * 4u);
                ldsm4(bf[p*4+0][1], bf[p*4+1][1], bf[p*4+2][1], bf[p*4+3][1],
                      sb_u + (uint32_t)(row * LDBW2 + kb2 + 4) * 4u);
            }
            #pragma unroll
            for (int mi = 0; mi < 2; mi++)
                #pragma unroll
                for (int ni = 0; ni < 8; ni++)
                    mma16(acc[mi][ni], af[mi], bf[ni]);
        }
        if (++st == NSTAGE) st = 0;
    }

    // ---- epilogue ----
    int c2 = (lane & 3) * 2;
    #pragma unroll
    for (int mi = 0; mi < 2; mi++) {
        #pragma unroll
        for (int ni = 0; ni < 8; ni++) {
            #pragma unroll
            for (int h = 0; h < 2; h++) {
                int row = row0 + wm + mi * 16 + r_ + h * 8;
                int col = col0 + wn + ni * 8 + c2;
                float v0 = acc[mi][ni][h * 2 + 0] + bias[col];
                float v1 = acc[mi][ni][h * 2 + 1] + bias[col + 1];
                if (EP == EP_GELU) {
                    v0 = 0.5f * v0 * (1.f + erff(v0 * 0.70710678118654752f));
                    v1 = 0.5f * v1 * (1.f + erff(v1 * 0.70710678118654752f));
                    *(uint32_t*)&Ch[(size_t)row * N + col] = packh2(v0, v1);
                } else if (EP == EP_RES) {
                    v0 += res[(size_t)row * N + col];
                    v1 += res[(size_t)row * N + col + 1];
                    *(float2*)&C[(size_t)row * N + col] = make_float2(v0, v1);
                } else if (EP == EP_HEADS) {
                    int mat = col >> 10;           // 0=Q,1=K,2=V (N=3072)
                    int cc  = col & 1023;
                    int bb = row >> 11, ss = row & 2047;
                    int hh = cc >> 6,  dd = cc & 63;
                    if (mat == 0) {                // Q pre-scaled by 0.125*log2e
                        *(uint32_t*)&Hq[(((size_t)(bb * Hc + hh)) * Sc + ss) * Dc + dd] =
                            packh2(v0 * QSCALE, v1 * QSCALE);
                    } else if (mat == 1) {         // K [B,H,S,D]
                        *(uint32_t*)&Hk[(((size_t)(bb * Hc + hh)) * Sc + ss) * Dc + dd] =
                            packh2(v0, v1);
                    } else {                       // V TRANSPOSED [B,H,D,S]
                        size_t base = ((size_t)(bb * Hc + hh)) * Dc;
                        Hv[(base + dd)     * Sc + ss] = __float2half_rn(v0);
                        Hv[(base + dd + 1) * Sc + ss] = __float2half_rn(v1);
                    }
                }
            }
        }
    }
}

// ---------------- fp16 TC flash attention: 64x64 tiles, 128 thr, cp.async + ldmatrix ----------------
#define LDW 36
#define Q_WORDS  (64 * LDW)                     // 2304
#define KV_WORDS (2 * 64 * LDW)                 // K + V per stage: 4608
#define ATTN_SMEM ((Q_WORDS + 2*KV_WORDS + 64*LDW) * 4)   // 55296 bytes

__global__ void __launch_bounds__(128, 3) attn_tc(const __half* __restrict__ Q,
                                                  const __half* __restrict__ K,
                                                  const __half* __restrict__ V,
                                                  __half* __restrict__ ctx) {
    extern __shared__ uint32_t smu[];
    uint32_t smem_u = (uint32_t)__cvta_generic_to_shared(smu);

    int tid = threadIdx.x, lane = tid & 31, w = tid >> 5;
    int r_ = lane >> 2, c_ = lane & 3;
    int qt = (int)gridDim.x - 1 - (int)blockIdx.x;   // heavy tiles first
    int bh = blockIdx.y;
    int q0 = qt * 64;

    const __half* Qb = Q + (size_t)bh * Sc * Dc;
    const __half* Kb = K + (size_t)bh * Sc * Dc;
    const __half* Vb = V + (size_t)bh * Dc * Sc;     // transposed [D][S]

    auto issue_kv = [&](int k0, int s) {
        uint32_t kbase = smem_u + (uint32_t)(Q_WORDS + s * KV_WORDS) * 4u;
        uint32_t vbase = kbase + (uint32_t)(64 * LDW) * 4u;
        #pragma unroll
        for (int it = 0; it < 4; it++) {
            int idx = tid + it * 128;
            int r = idx >> 3, wo = (idx & 7) * 4;
            cp16(kbase + (uint32_t)(r * LDW + wo) * 4u, Kb + (size_t)(k0 + r) * Dc + wo * 2);
            cp16(vbase + (uint32_t)(r * LDW + wo) * 4u, Vb + (size_t)r * Sc + k0 + wo * 2);
        }
        CP_COMMIT();
    };

    {
        #pragma unroll
        for (int it = 0; it < 4; it++) {
            int idx = tid + it * 128;
            int r = idx >> 3, wo = (idx & 7) * 4;
            cp16(smem_u + (uint32_t)(r * LDW + wo) * 4u, Qb + (size_t)(q0 + r) * Dc + wo * 2);
        }
        issue_kv(0, 0);   // commits Q copies too
    }

    float o[8][4];
    #pragma unroll
    for (int nf = 0; nf < 8; nf++)
        #pragma unroll
        for (int q = 0; q < 4; q++) o[nf][q] = 0.f;
    float m0 = -1e30f, m1 = -1e30f, l0 = 0.f, l1 = 0.f;

    uint32_t qf[4][4];
    int w16 = w * 16;
    uint32_t pwbase = smem_u + (uint32_t)(Q_WORDS + 2 * KV_WORDS + w16 * LDW) * 4u;
    uint32_t* pw = smu + Q_WORDS + 2 * KV_WORDS + w16 * LDW;

    int lrow = (lane & 7) + ((lane >> 3) & 1) * 8;   // A-pattern row
    int lcol = (lane >> 4) * 4;                      // A-pattern col offset
    int brow = (lane >> 3) * 8 + (lane & 7);         // B-pattern row

    for (int kt = 0; kt <= qt; kt++) {
        CP_WAIT0();
        __syncthreads();
        if (kt + 1 <= qt) issue_kv((kt + 1) * 64, (kt + 1) & 1);

        if (kt == 0) {    // Q A-frags once (pre-scaled by 0.125*log2e at producer)
            #pragma unroll
            for (int kc = 0; kc < 4; kc++) {
                int row = w16 + lrow;
                ldsm4(qf[kc][0], qf[kc][1], qf[kc][2], qf[kc][3],
                      smem_u + (uint32_t)(row * LDW + kc * 8 + lcol) * 4u);
            }
        }

        uint32_t kbase = smem_u + (uint32_t)(Q_WORDS + (kt & 1) * KV_WORDS) * 4u;
        uint32_t vbase = kbase + (uint32_t)(64 * LDW) * 4u;

        // ---- S(log2 domain) = (Q*0.125*log2e) K^T ----
        float sacc[8][4];
        #pragma unroll
        for (int nf = 0; nf < 8; nf++)
            #pragma unroll
            for (int q = 0; q < 4; q++) sacc[nf][q] = 0.f;
        #pragma unroll
        for (int kc = 0; kc < 4; kc++) {
            int kb = kc * 8;
            uint32_t bf[8][2];
            #pragma unroll
            for (int p = 0; p < 2; p++) {
                int row = p * 32 + brow;
                ldsm4(bf[p*4+0][0], bf[p*4+1][0], bf[p*4+2][0], bf[p*4+3][0],
                      kbase + (uint32_t)(row * LDW + kb) * 4u);
                ldsm4(bf[p*4+0][1], bf[p*4+1][1], bf[p*4+2][1], bf[p*4+3][1],
                      kbase + (uint32_t)(row * LDW + kb + 4) * 4u);
            }
            #pragma unroll
            for (int nf = 0; nf < 8; nf++)
                mma16(sacc[nf], qf[kc], bf[nf]);
        }

        // ---- causal mask on diagonal tile ----
        if (kt == qt) {
            int rr = w16 + r_;
            #pragma unroll
            for (int nf = 0; nf < 8; nf++) {
                int cb = nf * 8 + 2 * c_;
                if (cb     > rr)     sacc[nf][0] = -1e30f;
                if (cb + 1 > rr)     sacc[nf][1] = -1e30f;
                if (cb     > rr + 8) sacc[nf][2] = -1e30f;
                if (cb + 1 > rr + 8) sacc[nf][3] = -1e30f;
            }
        }

        // ---- online softmax (log2 domain: exp2) ----
        float mx0 = -1e30f, mx1 = -1e30f;
        #pragma unroll
        for (int nf = 0; nf < 8; nf++) {
            mx0 = fmaxf(mx0, fmaxf(sacc[nf][0], sacc[nf][1]));
            mx1 = fmaxf(mx1, fmaxf(sacc[nf][2], sacc[nf][3]));
        }
        mx0 = fmaxf(mx0, __shfl_xor_sync(0xffffffffu, mx0, 1));
        mx0 = fmaxf(mx0, __shfl_xor_sync(0xffffffffu, mx0, 2));
        mx1 = fmaxf(mx1, __shfl_xor_sync(0xffffffffu, mx1, 1));
        mx1 = fmaxf(mx1, __shfl_xor_sync(0xffffffffu, mx1, 2));
        float mn0 = fmaxf(m0, mx0), mn1 = fmaxf(m1, mx1);
        float es0 = exp2f(m0 - mn0), es1 = exp2f(m1 - mn1);
        m0 = mn0; m1 = mn1;
        float ls0 = 0.f, ls1 = 0.f;
        #pragma unroll
        for (int nf = 0; nf < 8; nf++) {
            sacc[nf][0] = exp2f(sacc[nf][0] - mn0);
            sacc[nf][1] = exp2f(sacc[nf][1] - mn0);
            sacc[nf][2] = exp2f(sacc[nf][2] - mn1);
            sacc[nf][3] = exp2f(sacc[nf][3] - mn1);
            ls0 += sacc[nf][0] + sacc[nf][1];
            ls1 += sacc[nf][2] + sacc[nf][3];
        }
        ls0 += __shfl_xor_sync(0xffffffffu, ls0, 1);
        ls0 += __shfl_xor_sync(0xffffffffu, ls0, 2);
        ls1 += __shfl_xor_sync(0xffffffffu, ls1, 1);
        ls1 += __shfl_xor_sync(0xffffffffu, ls1, 2);
        l0 = l0 * es0 + ls0;
        l1 = l1 * es1 + ls1;
        #pragma unroll
        for (int nf = 0; nf < 8; nf++) {
            o[nf][0] *= es0; o[nf][1] *= es0;
            o[nf][2] *= es1; o[nf][3] *= es1;
        }

        // ---- P -> warp-private smem as half2 ----
        #pragma unroll
        for (int nf = 0; nf < 8; nf++) {
            int wcol = nf * 4 + c_;
            pw[r_ * LDW + wcol]       = packh2(sacc[nf][0], sacc[nf][1]);
            pw[(r_ + 8) * LDW + wcol] = packh2(sacc[nf][2], sacc[nf][3]);
        }
        __syncwarp();

        // ---- O += P V ----
        #pragma unroll
        for (int kc = 0; kc < 4; kc++) {
            int kb = kc * 8;
            uint32_t af[4];
            ldsm4(af[0], af[1], af[2], af[3],
                  pwbase + (uint32_t)(lrow * LDW + kb + lcol) * 4u);
            uint32_t bf[8][2];
            #pragma unroll
            for (int p = 0; p < 2; p++) {
                int row = p * 32 + brow;
                ldsm4(bf[p*4+0][0], bf[p*4+1][0], bf[p*4+2][0], bf[p*4+3][0],
                      vbase + (uint32_t)(row * LDW + kb) * 4u);
                ldsm4(bf[p*4+0][1], bf[p*4+1][1], bf[p*4+2][1], bf[p*4+3][1],
                      vbase + (uint32_t)(row * LDW + kb + 4) * 4u);
            }
            #pragma unroll
            for (int nf = 0; nf < 8; nf++)
                mma16(o[nf], af, bf[nf]);
        }
        __syncwarp();
    }

    // ---- write ctx [B,S,E] as half ----
    int bb = bh >> 4, hh = bh & 15;
    int row0 = q0 + w16 + r_;
    float il0 = 1.f / l0, il1 = 1.f / l1;
    #pragma unroll
    for (int nf = 0; nf < 8; nf++) {
        int col = hh * 64 + nf * 8 + 2 * c_;
        *(uint32_t*)&ctx[((size_t)bb * Sc + row0) * Ec + col] =
            packh2(o[nf][0] * il0, o[nf][1] * il0);
        *(uint32_t*)&ctx[((size_t)bb * Sc + row0 + 8) * Ec + col] =
            packh2(o[nf][2] * il1, o[nf][3] * il1);
    }
}

// ---------------- launch ----------------
extern "C" void kernel_launch(void* const* d_in, const int* in_sizes, int n_in,
                              void* d_out, int out_size) {
    const float* x    = (const float*)d_in[0];
    const float* Wq   = (const float*)d_in[2];
    const float* bq   = (const float*)d_in[3];
    const float* Wk   = (const float*)d_in[4];
    const float* bk   = (const float*)d_in[5];
    const float* Wv   = (const float*)d_in[6];
    const float* bv   = (const float*)d_in[7];
    const float* Wo   = (const float*)d_in[8];
    const float* bo   = (const float*)d_in[9];
    const float* W1   = (const float*)d_in[10];
    const float* b1   = (const float*)d_in[11];
    const float* W2   = (const float*)d_in[12];
    const float* b2   = (const float*)d_in[13];
    const float* ln1g = (const float*)d_in[14];
    const float* ln1b = (const float*)d_in[15];
    const float* ln2g = (const float*)d_in[16];
    const float* ln2b = (const float*)d_in[17];
    float* out = (float*)d_out;

    __half *n_, *q_, *k_, *v_, *ctx_, *x2h_, *f1_;
    float *res_, *x2_, *bqkv_;
    uint32_t* wp_;
    cudaGetSymbolAddress((void**)&n_,   g_n);
    cudaGetSymbolAddress((void**)&q_,   g_q);
    cudaGetSymbolAddress((void**)&k_,   g_k);
    cudaGetSymbolAddress((void**)&v_,   g_v);
    cudaGetSymbolAddress((void**)&ctx_, g_ctx);
    cudaGetSymbolAddress((void**)&res_, g_res);
    cudaGetSymbolAddress((void**)&x2_,  g_x2);
    cudaGetSymbolAddress((void**)&x2h_, g_x2h);
    cudaGetSymbolAddress((void**)&f1_,  g_f1);
    cudaGetSymbolAddress((void**)&wp_,  g_wp);
    cudaGetSymbolAddress((void**)&bqkv_, g_bqkv);

    cudaFuncSetAttribute(hgemm<EP_HEADS>, cudaFuncAttributeMaxDynamicSharedMemorySize, TG_SMEM);
    cudaFuncSetAttribute(hgemm<EP_RES>,   cudaFuncAttributeMaxDynamicSharedMemorySize, TG_SMEM);
    cudaFuncSetAttribute(hgemm<EP_GELU>,  cudaFuncAttributeMaxDynamicSharedMemorySize, TG_SMEM);
    cudaFuncSetAttribute(attn_tc, cudaFuncAttributeMaxDynamicSharedMemorySize, ATTN_SMEM);

    // 0. convert + pack all weights to blocked fp16 layout (coalesced tile transpose)
    convert_all<<<CVT_BLOCKS + 3, 256>>>(Wq, Wk, Wv, Wo, W1, W2, bq, bk, bv, wp_, bqkv_);

    // 1. LN1 -> half (GEMM A only)
    ln_kernel<false, true><<<Mc, 256>>>(x, ln1g, ln1b, nullptr, n_);

    // 2. fused QKV projection (N=3072) -> Q(scaled)/K half [B,H,S,D], V half [B,H,D,S]
    hgemm<EP_HEADS><<<dim3(3072/BN, Mc/BM), 256, TG_SMEM>>>(n_, wp_ + WP_QKV, bqkv_, nullptr,
                                                            nullptr, nullptr, q_, k_, v_,
                                                            Mc, 3072, Ec);

    // 3. flash attention (fp16 TC, ldmatrix) -> ctx half [B,S,E]
    attn_tc<<<dim3(Sc/64, Bc*Hc), 128, ATTN_SMEM>>>(q_, k_, v_, ctx_);

    // 4. Wo projection + residual with x -> res fp32
    hgemm<EP_RES><<<dim3(Ec/BN, Mc/BM), 256, TG_SMEM>>>(ctx_, wp_ + WP_O, bo, x,
                                                        res_, nullptr, nullptr, nullptr, nullptr,
                                                        Mc, Ec, Ec);

    // 5. LN2 -> x2 fp32 (residual) + x2h half (GEMM A)
    ln_kernel<true, true><<<Mc, 256>>>(res_, ln2g, ln2b, x2_, x2h_);

    // 6. FFN1 + exact GELU -> f1 half
    hgemm<EP_GELU><<<dim3(Fc/BN, Mc/BM), 256, TG_SMEM>>>(x2h_, wp_ + WP_W1, b1, nullptr,
                                                         nullptr, f1_, nullptr, nullptr, nullptr,
                                                         Mc, Fc, Ec);

    // 7. FFN2 + bias + residual(x2) -> out fp32
    hgemm<EP_RES><<<dim3(Ec/BN, Mc/BM), 256, TG_SMEM>>>(f1_, wp_ + WP_W2, b2, x2_,
                                                        out, nullptr, nullptr, nullptr, nullptr,
                                                        Mc, Ec, Fc);
}

// round 14
// speedup vs baseline: 1.0679x; 1.0679x over previous
#include <cuda_runtime.h>
#include <cuda_fp16.h>
#include <math.h>
#include <stdint.h>

#define Bc 2
#define Sc 2048
#define Ec 1024
#define Hc 16
#define Dc 64
#define Fc 4096
#define Mc (Bc*Sc)          // 4096 rows
#define MB (1024*1024)

// ---------------- scratch (no cudaMalloc allowed) ----------------
__device__ __half g_n  [Mc*Ec];     // LN1 out (half, GEMM A)
__device__ __half g_q  [Mc*Ec];     // Q half [B,H,S,D], pre-scaled by 0.125*log2e
__device__ __half g_k  [Mc*Ec];     // K half [B,H,S,D]
__device__ __half g_v  [Mc*Ec];     // V half [B,H,D,S]  (TRANSPOSED)
__device__ __half g_ctx[Mc*Ec];     // attn out (half, GEMM A)
__device__ float  g_res[Mc*Ec];
__device__ float  g_x2 [Mc*Ec];     // LN2 out fp32 (residual)
__device__ __half g_x2h[Mc*Ec];     // LN2 out half (GEMM A)
__device__ __half g_f1 [Mc*Fc];     // GELU out (half, GEMM A)
__device__ uint32_t g_wp[6*MB];     // packed fp16 weights, k-interleaved half2 [K/2][N]
__device__ float  g_bqkv[3072];     // concat bias

// packed-weight word offsets
#define WP_QKV 0
#define WP_O   (3*MB/2)
#define WP_W1  (2*MB)
#define WP_W2  (4*MB)
#define WP_TOT (6*MB)

#define QSCALE 0.1803368801111729f   // 0.125 * log2(e)

// ---------------- helpers ----------------
__device__ __forceinline__ uint32_t packh2(float lo, float hi) {
    __half2 h = __floats2half2_rn(lo, hi);
    return *(uint32_t*)&h;
}

__device__ __forceinline__ void mma16(float* c, const uint32_t* a, const uint32_t* b) {
    asm volatile(
        "mma.sync.aligned.m16n8k16.row.col.f32.f16.f16.f32 "
        "{%0,%1,%2,%3}, {%4,%5,%6,%7}, {%8,%9}, {%0,%1,%2,%3};\n"
        : "+f"(c[0]), "+f"(c[1]), "+f"(c[2]), "+f"(c[3])
        : "r"(a[0]), "r"(a[1]), "r"(a[2]), "r"(a[3]),
          "r"(b[0]), "r"(b[1]));
}

__device__ __forceinline__ void ldsm4(uint32_t& r0, uint32_t& r1, uint32_t& r2, uint32_t& r3,
                                      uint32_t addr) {
    asm volatile("ldmatrix.sync.aligned.m8n8.x4.shared.b16 {%0,%1,%2,%3}, [%4];"
        : "=r"(r0), "=r"(r1), "=r"(r2), "=r"(r3) : "r"(addr));
}

__device__ __forceinline__ void cp16(uint32_t dst, const void* src) {
    asm volatile("cp.async.cg.shared.global [%0], [%1], 16;" :: "r"(dst), "l"(src));
}
#define CP_COMMIT() asm volatile("cp.async.commit_group;")
#define CP_WAIT0()  asm volatile("cp.async.wait_group 0;")
#define CP_WAIT1()  asm volatile("cp.async.wait_group 1;")

// ---------------- weight convert+pack: fp32 [K][N] -> half2 word [K/2][N] ----------------
__global__ void __launch_bounds__(256) convert_all(const float* __restrict__ Wq,
                                                   const float* __restrict__ Wk,
                                                   const float* __restrict__ Wv,
                                                   const float* __restrict__ Wo,
                                                   const float* __restrict__ W1,
                                                   const float* __restrict__ W2,
                                                   const float* __restrict__ bq,
                                                   const float* __restrict__ bk,
                                                   const float* __restrict__ bv,
                                                   uint32_t* __restrict__ wp,
                                                   float* __restrict__ bqkv) {
    long wi = ((long)blockIdx.x * 256 + threadIdx.x) * 4;   // 4 words along n
    if (wi < WP_TOT) {
        const float *r0;
        long rstride;
        if (wi < WP_O) {                       // Wqkv concat: [512][3072]
            long k2 = wi / 3072, n = wi % 3072;
            int mat = (int)(n >> 10);
            const float* W = (mat == 0) ? Wq : (mat == 1) ? Wk : Wv;
            r0 = W + (2 * k2) * 1024 + (n & 1023);
            rstride = 1024;
        } else if (wi < WP_W1) {               // Wo: [512][1024]
            long off = wi - WP_O;
            r0 = Wo + (2 * (off >> 10)) * 1024 + (off & 1023);
            rstride = 1024;
        } else if (wi < WP_W2) {               // W1: [512][4096]
            long off = wi - WP_W1;
            r0 = W1 + (2 * (off >> 12)) * 4096 + (off & 4095);
            rstride = 4096;
        } else {                               // W2: [2048][1024]
            long off = wi - WP_W2;
            r0 = W2 + (2 * (off >> 10)) * 1024 + (off & 1023);
            rstride = 1024;
        }
        float4 e = *(const float4*)r0;
        float4 o = *(const float4*)(r0 + rstride);
        uint4 w;
        w.x = packh2(e.x, o.x);
        w.y = packh2(e.y, o.y);
        w.z = packh2(e.z, o.z);
        w.w = packh2(e.w, o.w);
        *(uint4*)(wp + wi) = w;
    } else if (wi < WP_TOT + 3072) {           // bias concat (fp32 copy)
        long j = wi - WP_TOT;
        int mat = (int)(j >> 10);
        const float* B = (mat == 0) ? bq : (mat == 1) ? bk : bv;
        *(float4*)(bqkv + j) = *(const float4*)(B + (j & 1023));
    }
}

// ---------------- LayerNorm: optional fp32 / half outputs ----------------
template<bool WF, bool WH>
__global__ void __launch_bounds__(256) ln_kernel(const float* __restrict__ x,
                                                 const float* __restrict__ g,
                                                 const float* __restrict__ b,
                                                 float* __restrict__ out_f,
                                                 __half* __restrict__ out_h) {
    int row = blockIdx.x;
    int tid = threadIdx.x;
    const float4* xr = (const float4*)(x + (size_t)row * Ec);
    float4 xv = xr[tid];
    float s  = xv.x + xv.y + xv.z + xv.w;
    float sq = xv.x*xv.x + xv.y*xv.y + xv.z*xv.z + xv.w*xv.w;
    #pragma unroll
    for (int o = 16; o; o >>= 1) {
        s  += __shfl_xor_sync(0xffffffffu, s,  o);
        sq += __shfl_xor_sync(0xffffffffu, sq, o);
    }
    __shared__ float ws[8], wq[8];
    __shared__ float s_mu, s_rstd;
    int lane = tid & 31, wid = tid >> 5;
    if (lane == 0) { ws[wid] = s; wq[wid] = sq; }
    __syncthreads();
    if (tid == 0) {
        float S = 0.f, Q = 0.f;
        #pragma unroll
        for (int i = 0; i < 8; i++) { S += ws[i]; Q += wq[i]; }
        float mu  = S * (1.0f / Ec);
        float var = Q * (1.0f / Ec) - mu * mu;
        s_mu = mu;
        s_rstd = rsqrtf(var + 1e-5f);
    }
    __syncthreads();
    float mu = s_mu, rstd = s_rstd;
    float4 gv = ((const float4*)g)[tid];
    float4 bv = ((const float4*)b)[tid];
    float4 ov;
    ov.x = (xv.x - mu) * rstd * gv.x + bv.x;
    ov.y = (xv.y - mu) * rstd * gv.y + bv.y;
    ov.z = (xv.z - mu) * rstd * gv.z + bv.z;
    ov.w = (xv.w - mu) * rstd * gv.w + bv.w;
    if (WF) ((float4*)(out_f + (size_t)row * Ec))[tid] = ov;
    if (WH) {
        uint2 hw;
        hw.x = packh2(ov.x, ov.y);
        hw.y = packh2(ov.z, ov.w);
        *(uint2*)(out_h + (size_t)row * Ec + tid * 4) = hw;
    }
}

// ---------------- fp16 TC GEMM: 128x128x32, 8 warps (2x4), 3-stage cp.async ----------------
enum { EP_PLAIN = 0, EP_HEADS = 1, EP_RES = 2, EP_GELU = 3 };

#define BM 128
#define BN 128
#define BKH 32                       // k-tile in halves
#define LDA2 20                      // As row stride in half2 words
#define LDB2 136                     // Bs row stride in words
#define STG_A2 (BM * LDA2)           // 2560 words
#define STG_B2 (16 * LDB2)           // 2176 words
#define STG2   (STG_A2 + STG_B2)     // 4736 words
#define NSTAGE 3
#define TG_SMEM (NSTAGE * STG2 * 4)  // 56832 bytes

template<int EP>
__global__ void __launch_bounds__(256, 2) hgemm(const __half* __restrict__ A,
                                                const uint32_t* __restrict__ Wp,
                                                const float* __restrict__ bias,
                                                const float* __restrict__ res,
                                                float* __restrict__ C,
                                                __half* __restrict__ Ch,
                                                __half* __restrict__ Hq,
                                                __half* __restrict__ Hk,
                                                __half* __restrict__ Hv,
                                                int M, int N, int K) {
    extern __shared__ uint32_t sh[];
    uint32_t smem_u = (uint32_t)__cvta_generic_to_shared(sh);

    int tid  = threadIdx.x;
    int lane = tid & 31;
    int w    = tid >> 5;
    int wm   = (w & 1) * 64;     // 2 warps along M, 64 rows each
    int wn   = (w >> 1) * 32;    // 4 warps along N, 32 cols each
    int row0 = blockIdx.y * BM;
    int col0 = blockIdx.x * BN;

    const __half* Ab = A + (size_t)row0 * K;
    const uint32_t* Wb = Wp + col0;

    auto issue = [&](int kt, int s) {
        uint32_t sa = smem_u + (uint32_t)(s * STG2) * 4u;
        uint32_t sb = sa + (uint32_t)STG_A2 * 4u;
        int k0 = kt * BKH;          // halves
        int k2b = kt * 16;          // half2 rows in Wp
        #pragma unroll
        for (int j = 0; j < 2; j++) {
            int idx = tid + j * 256;
            int r  = idx >> 2, wo = (idx & 3) * 4;
            cp16(sa + (uint32_t)(r * LDA2 + wo) * 4u, Ab + (size_t)r * K + k0 + wo * 2);
            int kr = idx >> 5, nw = (idx & 31) * 4;
            cp16(sb + (uint32_t)(kr * LDB2 + nw) * 4u, Wb + (size_t)(k2b + kr) * N + nw);
        }
        CP_COMMIT();
    };

    float acc[4][4][4];
    #pragma unroll
    for (int mi = 0; mi < 4; mi++)
        #pragma unroll
        for (int ni = 0; ni < 4; ni++)
            #pragma unroll
            for (int q = 0; q < 4; q++) acc[mi][ni][q] = 0.f;

    int nk = K / BKH;
    issue(0, 0);
    issue(1, 1);

    int r_ = lane >> 2, c_ = lane & 3;
    int lrow = (lane & 7) + ((lane >> 3) & 1) * 8;   // ldmatrix A row pattern
    int lcol = (lane >> 4) * 4;                      // ldmatrix A col offset (words)

    int st = 0;
    for (int kt = 0; kt < nk; kt++) {
        if (kt + 1 < nk) { CP_WAIT1(); } else { CP_WAIT0(); }
        __syncthreads();
        if (kt + 2 < nk) {
            int s2 = st + 2; if (s2 >= NSTAGE) s2 -= NSTAGE;
            issue(kt + 2, s2);
        }

        uint32_t sa_u = smem_u + (uint32_t)(st * STG2) * 4u;
        const uint32_t* Sb = sh + st * STG2 + STG_A2;

        #pragma unroll
        for (int ks = 0; ks < 2; ks++) {
            int kb2 = ks * 8;
            uint32_t af[4][4], bf[4][2];
            #pragma unroll
            for (int mi = 0; mi < 4; mi++) {
                int row = wm + mi * 16 + lrow;
                ldsm4(af[mi][0], af[mi][1], af[mi][2], af[mi][3],
                      sa_u + (uint32_t)(row * LDA2 + kb2 + lcol) * 4u);
            }
            #pragma unroll
            for (int ni = 0; ni < 4; ni++) {
                int n = wn + ni * 8 + r_;
                bf[ni][0] = Sb[(kb2 + c_) * LDB2 + n];
                bf[ni][1] = Sb[(kb2 + c_ + 4) * LDB2 + n];
            }
            #pragma unroll
            for (int mi = 0; mi < 4; mi++)
                #pragma unroll
                for (int ni = 0; ni < 4; ni++)
                    mma16(acc[mi][ni], af[mi], bf[ni]);
        }
        if (++st == NSTAGE) st = 0;
    }

    // ---- epilogue ----
    int c2 = (lane & 3) * 2;
    #pragma unroll
    for (int mi = 0; mi < 4; mi++) {
        #pragma unroll
        for (int ni = 0; ni < 4; ni++) {
            #pragma unroll
            for (int h = 0; h < 2; h++) {
                int row = row0 + wm + mi * 16 + r_ + h * 8;
                int col = col0 + wn + ni * 8 + c2;
                float v0 = acc[mi][ni][h * 2 + 0] + bias[col];
                float v1 = acc[mi][ni][h * 2 + 1] + bias[col + 1];
                if (EP == EP_GELU) {
                    v0 = 0.5f * v0 * (1.f + erff(v0 * 0.70710678118654752f));
                    v1 = 0.5f * v1 * (1.f + erff(v1 * 0.70710678118654752f));
                    *(uint32_t*)&Ch[(size_t)row * N + col] = packh2(v0, v1);
                } else if (EP == EP_RES) {
                    v0 += res[(size_t)row * N + col];
                    v1 += res[(size_t)row * N + col + 1];
                    *(float2*)&C[(size_t)row * N + col] = make_float2(v0, v1);
                } else if (EP == EP_HEADS) {
                    int mat = col >> 10;           // 0=Q,1=K,2=V (N=3072)
                    int cc  = col & 1023;
                    int bb = row >> 11, ss = row & 2047;
                    int hh = cc >> 6,  dd = cc & 63;
                    if (mat == 0) {                // Q pre-scaled by 0.125*log2e
                        *(uint32_t*)&Hq[(((size_t)(bb * Hc + hh)) * Sc + ss) * Dc + dd] =
                            packh2(v0 * QSCALE, v1 * QSCALE);
                    } else if (mat == 1) {         // K [B,H,S,D]
                        *(uint32_t*)&Hk[(((size_t)(bb * Hc + hh)) * Sc + ss) * Dc + dd] =
                            packh2(v0, v1);
                    } else {                       // V TRANSPOSED [B,H,D,S]
                        size_t base = ((size_t)(bb * Hc + hh)) * Dc;
                        Hv[(base + dd)     * Sc + ss] = __float2half_rn(v0);
                        Hv[(base + dd + 1) * Sc + ss] = __float2half_rn(v1);
                    }
                }
            }
        }
    }
}

// ---------------- fp16 TC flash attention: 64x64 tiles, 128 thr, cp.async + ldmatrix ----------------
#define LDW 36
#define Q_WORDS  (64 * LDW)                     // 2304
#define KV_WORDS (2 * 64 * LDW)                 // K + V per stage: 4608
#define ATTN_SMEM ((Q_WORDS + 2*KV_WORDS + 64*LDW) * 4)   // 55296 bytes

__global__ void __launch_bounds__(128, 3) attn_tc(const __half* __restrict__ Q,
                                                  const __half* __restrict__ K,
                                                  const __half* __restrict__ V,
                                                  __half* __restrict__ ctx) {
    extern __shared__ uint32_t smu[];
    uint32_t smem_u = (uint32_t)__cvta_generic_to_shared(smu);

    int tid = threadIdx.x, lane = tid & 31, w = tid >> 5;
    int r_ = lane >> 2, c_ = lane & 3;
    int qt = (int)gridDim.x - 1 - (int)blockIdx.x;   // heavy tiles first
    int bh = blockIdx.y;
    int q0 = qt * 64;

    const __half* Qb = Q + (size_t)bh * Sc * Dc;
    const __half* Kb = K + (size_t)bh * Sc * Dc;
    const __half* Vb = V + (size_t)bh * Dc * Sc;     // transposed [D][S]

    auto issue_kv = [&](int k0, int s) {
        uint32_t kbase = smem_u + (uint32_t)(Q_WORDS + s * KV_WORDS) * 4u;
        uint32_t vbase = kbase + (uint32_t)(64 * LDW) * 4u;
        #pragma unroll
        for (int it = 0; it < 4; it++) {
            int idx = tid + it * 128;
            int r = idx >> 3, wo = (idx & 7) * 4;
            cp16(kbase + (uint32_t)(r * LDW + wo) * 4u, Kb + (size_t)(k0 + r) * Dc + wo * 2);
            cp16(vbase + (uint32_t)(r * LDW + wo) * 4u, Vb + (size_t)r * Sc + k0 + wo * 2);
        }
        CP_COMMIT();
    };

    {
        #pragma unroll
        for (int it = 0; it < 4; it++) {
            int idx = tid + it * 128;
            int r = idx >> 3, wo = (idx & 7) * 4;
            cp16(smem_u + (uint32_t)(r * LDW + wo) * 4u, Qb + (size_t)(q0 + r) * Dc + wo * 2);
        }
        issue_kv(0, 0);   // commits Q copies too
    }

    float o[8][4];
    #pragma unroll
    for (int nf = 0; nf < 8; nf++)
        #pragma unroll
        for (int q = 0; q < 4; q++) o[nf][q] = 0.f;
    float m0 = -1e30f, m1 = -1e30f, l0 = 0.f, l1 = 0.f;

    uint32_t qf[4][4];
    int w16 = w * 16;
    uint32_t pwbase = smem_u + (uint32_t)(Q_WORDS + 2 * KV_WORDS + w16 * LDW) * 4u;
    uint32_t* pw = smu + Q_WORDS + 2 * KV_WORDS + w16 * LDW;

    int lrow = (lane & 7) + ((lane >> 3) & 1) * 8;   // A-pattern row
    int lcol = (lane >> 4) * 4;                      // A-pattern col offset
    int brow = (lane >> 3) * 8 + (lane & 7);         // B-pattern row

    for (int kt = 0; kt <= qt; kt++) {
        CP_WAIT0();
        __syncthreads();
        if (kt + 1 <= qt) issue_kv((kt + 1) * 64, (kt + 1) & 1);

        if (kt == 0) {    // Q A-frags once (pre-scaled by 0.125*log2e at producer)
            #pragma unroll
            for (int kc = 0; kc < 4; kc++) {
                int row = w16 + lrow;
                ldsm4(qf[kc][0], qf[kc][1], qf[kc][2], qf[kc][3],
                      smem_u + (uint32_t)(row * LDW + kc * 8 + lcol) * 4u);
            }
        }

        uint32_t kbase = smem_u + (uint32_t)(Q_WORDS + (kt & 1) * KV_WORDS) * 4u;
        uint32_t vbase = kbase + (uint32_t)(64 * LDW) * 4u;

        // ---- S(log2 domain) = (Q*0.125*log2e) K^T ----
        float sacc[8][4];
        #pragma unroll
        for (int nf = 0; nf < 8; nf++)
            #pragma unroll
            for (int q = 0; q < 4; q++) sacc[nf][q] = 0.f;
        #pragma unroll
        for (int kc = 0; kc < 4; kc++) {
            int kb = kc * 8;
            uint32_t bf[8][2];
            #pragma unroll
            for (int p = 0; p < 2; p++) {
                int row = p * 32 + brow;
                ldsm4(bf[p*4+0][0], bf[p*4+1][0], bf[p*4+2][0], bf[p*4+3][0],
                      kbase + (uint32_t)(row * LDW + kb) * 4u);
                ldsm4(bf[p*4+0][1], bf[p*4+1][1], bf[p*4+2][1], bf[p*4+3][1],
                      kbase + (uint32_t)(row * LDW + kb + 4) * 4u);
            }
            #pragma unroll
            for (int nf = 0; nf < 8; nf++)
                mma16(sacc[nf], qf[kc], bf[nf]);
        }

        // ---- causal mask on diagonal tile ----
        if (kt == qt) {
            int rr = w16 + r_;
            #pragma unroll
            for (int nf = 0; nf < 8; nf++) {
                int cb = nf * 8 + 2 * c_;
                if (cb     > rr)     sacc[nf][0] = -1e30f;
                if (cb + 1 > rr)     sacc[nf][1] = -1e30f;
                if (cb     > rr + 8) sacc[nf][2] = -1e30f;
                if (cb + 1 > rr + 8) sacc[nf][3] = -1e30f;
            }
        }

        // ---- online softmax (log2 domain: exp2) ----
        float mx0 = -1e30f, mx1 = -1e30f;
        #pragma unroll
        for (int nf = 0; nf < 8; nf++) {
            mx0 = fmaxf(mx0, fmaxf(sacc[nf][0], sacc[nf][1]));
            mx1 = fmaxf(mx1, fmaxf(sacc[nf][2], sacc[nf][3]));
        }
        mx0 = fmaxf(mx0, __shfl_xor_sync(0xffffffffu, mx0, 1));
        mx0 = fmaxf(mx0, __shfl_xor_sync(0xffffffffu, mx0, 2));
        mx1 = fmaxf(mx1, __shfl_xor_sync(0xffffffffu, mx1, 1));
        mx1 = fmaxf(mx1, __shfl_xor_sync(0xffffffffu, mx1, 2));
        float mn0 = fmaxf(m0, mx0), mn1 = fmaxf(m1, mx1);
        float es0 = exp2f(m0 - mn0), es1 = exp2f(m1 - mn1);
        m0 = mn0; m1 = mn1;
        float ls0 = 0.f, ls1 = 0.f;
        #pragma unroll
        for (int nf = 0; nf < 8; nf++) {
            sacc[nf][0] = exp2f(sacc[nf][0] - mn0);
            sacc[nf][1] = exp2f(sacc[nf][1] - mn0);
            sacc[nf][2] = exp2f(sacc[nf][2] - mn1);
            sacc[nf][3] = exp2f(sacc[nf][3] - mn1);
            ls0 += sacc[nf][0] + sacc[nf][1];
            ls1 += sacc[nf][2] + sacc[nf][3];
        }
        ls0 += __shfl_xor_sync(0xffffffffu, ls0, 1);
        ls0 += __shfl_xor_sync(0xffffffffu, ls0, 2);
        ls1 += __shfl_xor_sync(0xffffffffu, ls1, 1);
        ls1 += __shfl_xor_sync(0xffffffffu, ls1, 2);
        l0 = l0 * es0 + ls0;
        l1 = l1 * es1 + ls1;
        #pragma unroll
        for (int nf = 0; nf < 8; nf++) {
            o[nf][0] *= es0; o[nf][1] *= es0;
            o[nf][2] *= es1; o[nf][3] *= es1;
        }

        // ---- P -> warp-private smem as half2 ----
        #pragma unroll
        for (int nf = 0; nf < 8; nf++) {
            int wcol = nf * 4 + c_;
            pw[r_ * LDW + wcol]       = packh2(sacc[nf][0], sacc[nf][1]);
            pw[(r_ + 8) * LDW + wcol] = packh2(sacc[nf][2], sacc[nf][3]);
        }
        __syncwarp();

        // ---- O += P V ----
        #pragma unroll
        for (int kc = 0; kc < 4; kc++) {
            int kb = kc * 8;
            uint32_t af[4];
            ldsm4(af[0], af[1], af[2], af[3],
                  pwbase + (uint32_t)(lrow * LDW + kb + lcol) * 4u);
            uint32_t bf[8][2];
            #pragma unroll
            for (int p = 0; p < 2; p++) {
                int row = p * 32 + brow;
                ldsm4(bf[p*4+0][0], bf[p*4+1][0], bf[p*4+2][0], bf[p*4+3][0],
                      vbase + (uint32_t)(row * LDW + kb) * 4u);
                ldsm4(bf[p*4+0][1], bf[p*4+1][1], bf[p*4+2][1], bf[p*4+3][1],
                      vbase + (uint32_t)(row * LDW + kb + 4) * 4u);
            }
            #pragma unroll
            for (int nf = 0; nf < 8; nf++)
                mma16(o[nf], af, bf[nf]);
        }
        __syncwarp();
    }

    // ---- write ctx [B,S,E] as half ----
    int bb = bh >> 4, hh = bh & 15;
    int row0 = q0 + w16 + r_;
    float il0 = 1.f / l0, il1 = 1.f / l1;
    #pragma unroll
    for (int nf = 0; nf < 8; nf++) {
        int col = hh * 64 + nf * 8 + 2 * c_;
        *(uint32_t*)&ctx[((size_t)bb * Sc + row0) * Ec + col] =
            packh2(o[nf][0] * il0, o[nf][1] * il0);
        *(uint32_t*)&ctx[((size_t)bb * Sc + row0 + 8) * Ec + col] =
            packh2(o[nf][2] * il1, o[nf][3] * il1);
    }
}

// ---------------- launch ----------------
extern "C" void kernel_launch(void* const* d_in, const int* in_sizes, int n_in,
                              void* d_out, int out_size) {
    const float* x    = (const float*)d_in[0];
    const float* Wq   = (const float*)d_in[2];
    const float* bq   = (const float*)d_in[3];
    const float* Wk   = (const float*)d_in[4];
    const float* bk   = (const float*)d_in[5];
    const float* Wv   = (const float*)d_in[6];
    const float* bv   = (const float*)d_in[7];
    const float* Wo   = (const float*)d_in[8];
    const float* bo   = (const float*)d_in[9];
    const float* W1   = (const float*)d_in[10];
    const float* b1   = (const float*)d_in[11];
    const float* W2   = (const float*)d_in[12];
    const float* b2   = (const float*)d_in[13];
    const float* ln1g = (const float*)d_in[14];
    const float* ln1b = (const float*)d_in[15];
    const float* ln2g = (const float*)d_in[16];
    const float* ln2b = (const float*)d_in[17];
    float* out = (float*)d_out;

    __half *n_, *q_, *k_, *v_, *ctx_, *x2h_, *f1_;
    float *res_, *x2_, *bqkv_;
    uint32_t* wp_;
    cudaGetSymbolAddress((void**)&n_,   g_n);
    cudaGetSymbolAddress((void**)&q_,   g_q);
    cudaGetSymbolAddress((void**)&k_,   g_k);
    cudaGetSymbolAddress((void**)&v_,   g_v);
    cudaGetSymbolAddress((void**)&ctx_, g_ctx);
    cudaGetSymbolAddress((void**)&res_, g_res);
    cudaGetSymbolAddress((void**)&x2_,  g_x2);
    cudaGetSymbolAddress((void**)&x2h_, g_x2h);
    cudaGetSymbolAddress((void**)&f1_,  g_f1);
    cudaGetSymbolAddress((void**)&wp_,  g_wp);
    cudaGetSymbolAddress((void**)&bqkv_, g_bqkv);

    cudaFuncSetAttribute(hgemm<EP_HEADS>, cudaFuncAttributeMaxDynamicSharedMemorySize, TG_SMEM);
    cudaFuncSetAttribute(hgemm<EP_RES>,   cudaFuncAttributeMaxDynamicSharedMemorySize, TG_SMEM);
    cudaFuncSetAttribute(hgemm<EP_GELU>,  cudaFuncAttributeMaxDynamicSharedMemorySize, TG_SMEM);
    cudaFuncSetAttribute(attn_tc, cudaFuncAttributeMaxDynamicSharedMemorySize, ATTN_SMEM);

    // 0. convert + pack all weights to fp16 k-interleaved layout (one launch)
    long cblocks = ((WP_TOT + 3072) / 4 + 255) / 256;
    convert_all<<<(int)cblocks, 256>>>(Wq, Wk, Wv, Wo, W1, W2, bq, bk, bv, wp_, bqkv_);

    // 1. LN1 -> half (GEMM A only)
    ln_kernel<false, true><<<Mc, 256>>>(x, ln1g, ln1b, nullptr, n_);

    // 2. fused QKV projection (N=3072) -> Q(scaled)/K half [B,H,S,D], V half [B,H,D,S]
    hgemm<EP_HEADS><<<dim3(3072/BN, Mc/BM), 256, TG_SMEM>>>(n_, wp_ + WP_QKV, bqkv_, nullptr,
                                                            nullptr, nullptr, q_, k_, v_,
                                                            Mc, 3072, Ec);

    // 3. flash attention (fp16 TC, ldmatrix) -> ctx half [B,S,E]
    attn_tc<<<dim3(Sc/64, Bc*Hc), 128, ATTN_SMEM>>>(q_, k_, v_, ctx_);

    // 4. Wo projection + residual with x -> res fp32
    hgemm<EP_RES><<<dim3(Ec/BN, Mc/BM), 256, TG_SMEM>>>(ctx_, wp_ + WP_O, bo, x,
                                                        res_, nullptr, nullptr, nullptr, nullptr,
                                                        Mc, Ec, Ec);

    // 5. LN2 -> x2 fp32 (residual) + x2h half (GEMM A)
    ln_kernel<true, true><<<Mc, 256>>>(res_, ln2g, ln2b, x2_, x2h_);

    // 6. FFN1 + exact GELU -> f1 half
    hgemm<EP_GELU><<<dim3(Fc/BN, Mc/BM), 256, TG_SMEM>>>(x2h_, wp_ + WP_W1, b1, nullptr,
                                                         nullptr, f1_, nullptr, nullptr, nullptr,
                                                         Mc, Fc, Ec);

    // 7. FFN2 + bias + residual(x2) -> out fp32
    hgemm<EP_RES><<<dim3(Ec/BN, Mc/BM), 256, TG_SMEM>>>(f1_, wp_ + WP_W2, b2, x2_,
                                                        out, nullptr, nullptr, nullptr, nullptr,
                                                        Mc, Ec, Fc);
}

// round 15
// speedup vs baseline: 1.1485x; 1.0755x over previous
#include <cuda_runtime.h>
#include <cuda_fp16.h>
#include <math.h>
#include <stdint.h>

#define Bc 2
#define Sc 2048
#define Ec 1024
#define Hc 16
#define Dc 64
#define Fc 4096
#define Mc (Bc*Sc)          // 4096 rows
#define MB (1024*1024)

// ---------------- scratch (no cudaMalloc allowed) ----------------
__device__ __half g_n  [Mc*Ec];     // LN1 out (half, GEMM A)
__device__ __half g_q  [Mc*Ec];     // Q half [B,H,S,D], pre-scaled by 0.125*log2e
__device__ __half g_k  [Mc*Ec];     // K half [B,H,S,D]
__device__ __half g_v  [Mc*Ec];     // V half [B,H,D,S]  (TRANSPOSED)
__device__ __half g_ctx[Mc*Ec];     // attn out (half, GEMM A)
__device__ float  g_res[Mc*Ec];
__device__ float  g_x2 [Mc*Ec];     // LN2 out fp32 (residual)
__device__ __half g_x2h[Mc*Ec];     // LN2 out half (GEMM A)
__device__ __half g_f1 [Mc*Fc];     // GELU out (half, GEMM A)
__device__ uint32_t g_wp[6*MB];     // packed fp16 weights, k-interleaved half2 [K/2][N]
__device__ float  g_bqkv[3072];     // concat bias

// packed-weight word offsets
#define WP_QKV 0
#define WP_O   (3*MB/2)
#define WP_W1  (2*MB)
#define WP_W2  (4*MB)
#define WP_TOT (6*MB)

#define QSCALE 0.1803368801111729f   // 0.125 * log2(e)

// ---------------- helpers ----------------
__device__ __forceinline__ uint32_t packh2(float lo, float hi) {
    __half2 h = __floats2half2_rn(lo, hi);
    return *(uint32_t*)&h;
}

__device__ __forceinline__ void mma16(float* c, const uint32_t* a, const uint32_t* b) {
    asm volatile(
        "mma.sync.aligned.m16n8k16.row.col.f32.f16.f16.f32 "
        "{%0,%1,%2,%3}, {%4,%5,%6,%7}, {%8,%9}, {%0,%1,%2,%3};\n"
        : "+f"(c[0]), "+f"(c[1]), "+f"(c[2]), "+f"(c[3])
        : "r"(a[0]), "r"(a[1]), "r"(a[2]), "r"(a[3]),
          "r"(b[0]), "r"(b[1]));
}

__device__ __forceinline__ void ldsm4(uint32_t& r0, uint32_t& r1, uint32_t& r2, uint32_t& r3,
                                      uint32_t addr) {
    asm volatile("ldmatrix.sync.aligned.m8n8.x4.shared.b16 {%0,%1,%2,%3}, [%4];"
        : "=r"(r0), "=r"(r1), "=r"(r2), "=r"(r3) : "r"(addr));
}

__device__ __forceinline__ void cp16(uint32_t dst, const void* src) {
    asm volatile("cp.async.cg.shared.global [%0], [%1], 16;" :: "r"(dst), "l"(src));
}
#define CP_COMMIT() asm volatile("cp.async.commit_group;")
#define CP_WAIT0()  asm volatile("cp.async.wait_group 0;")
#define CP_WAIT1()  asm volatile("cp.async.wait_group 1;")

// ---------------- weight convert+pack: fp32 [K][N] -> half2 word [K/2][N] ----------------
__global__ void __launch_bounds__(256) convert_all(const float* __restrict__ Wq,
                                                   const float* __restrict__ Wk,
                                                   const float* __restrict__ Wv,
                                                   const float* __restrict__ Wo,
                                                   const float* __restrict__ W1,
                                                   const float* __restrict__ W2,
                                                   const float* __restrict__ bq,
                                                   const float* __restrict__ bk,
                                                   const float* __restrict__ bv,
                                                   uint32_t* __restrict__ wp,
                                                   float* __restrict__ bqkv) {
    long wi = ((long)blockIdx.x * 256 + threadIdx.x) * 4;   // 4 words along n
    if (wi < WP_TOT) {
        const float *r0;
        long rstride;
        if (wi < WP_O) {                       // Wqkv concat: [512][3072]
            long k2 = wi / 3072, n = wi % 3072;
            int mat = (int)(n >> 10);
            const float* W = (mat == 0) ? Wq : (mat == 1) ? Wk : Wv;
            r0 = W + (2 * k2) * 1024 + (n & 1023);
            rstride = 1024;
        } else if (wi < WP_W1) {               // Wo: [512][1024]
            long off = wi - WP_O;
            r0 = Wo + (2 * (off >> 10)) * 1024 + (off & 1023);
            rstride = 1024;
        } else if (wi < WP_W2) {               // W1: [512][4096]
            long off = wi - WP_W1;
            r0 = W1 + (2 * (off >> 12)) * 4096 + (off & 4095);
            rstride = 4096;
        } else {                               // W2: [2048][1024]
            long off = wi - WP_W2;
            r0 = W2 + (2 * (off >> 10)) * 1024 + (off & 1023);
            rstride = 1024;
        }
        float4 e = *(const float4*)r0;
        float4 o = *(const float4*)(r0 + rstride);
        uint4 w;
        w.x = packh2(e.x, o.x);
        w.y = packh2(e.y, o.y);
        w.z = packh2(e.z, o.z);
        w.w = packh2(e.w, o.w);
        *(uint4*)(wp + wi) = w;
    } else if (wi < WP_TOT + 3072) {           // bias concat (fp32 copy)
        long j = wi - WP_TOT;
        int mat = (int)(j >> 10);
        const float* B = (mat == 0) ? bq : (mat == 1) ? bk : bv;
        *(float4*)(bqkv + j) = *(const float4*)(B + (j & 1023));
    }
}

// ---------------- LayerNorm: optional fp32 / half outputs ----------------
template<bool WF, bool WH>
__global__ void __launch_bounds__(256) ln_kernel(const float* __restrict__ x,
                                                 const float* __restrict__ g,
                                                 const float* __restrict__ b,
                                                 float* __restrict__ out_f,
                                                 __half* __restrict__ out_h) {
    int row = blockIdx.x;
    int tid = threadIdx.x;
    const float4* xr = (const float4*)(x + (size_t)row * Ec);
    float4 xv = xr[tid];
    float s  = xv.x + xv.y + xv.z + xv.w;
    float sq = xv.x*xv.x + xv.y*xv.y + xv.z*xv.z + xv.w*xv.w;
    #pragma unroll
    for (int o = 16; o; o >>= 1) {
        s  += __shfl_xor_sync(0xffffffffu, s,  o);
        sq += __shfl_xor_sync(0xffffffffu, sq, o);
    }
    __shared__ float ws[8], wq[8];
    __shared__ float s_mu, s_rstd;
    int lane = tid & 31, wid = tid >> 5;
    if (lane == 0) { ws[wid] = s; wq[wid] = sq; }
    __syncthreads();
    if (tid == 0) {
        float S = 0.f, Q = 0.f;
        #pragma unroll
        for (int i = 0; i < 8; i++) { S += ws[i]; Q += wq[i]; }
        float mu  = S * (1.0f / Ec);
        float var = Q * (1.0f / Ec) - mu * mu;
        s_mu = mu;
        s_rstd = rsqrtf(var + 1e-5f);
    }
    __syncthreads();
    float mu = s_mu, rstd = s_rstd;
    float4 gv = ((const float4*)g)[tid];
    float4 bv = ((const float4*)b)[tid];
    float4 ov;
    ov.x = (xv.x - mu) * rstd * gv.x + bv.x;
    ov.y = (xv.y - mu) * rstd * gv.y + bv.y;
    ov.z = (xv.z - mu) * rstd * gv.z + bv.z;
    ov.w = (xv.w - mu) * rstd * gv.w + bv.w;
    if (WF) ((float4*)(out_f + (size_t)row * Ec))[tid] = ov;
    if (WH) {
        uint2 hw;
        hw.x = packh2(ov.x, ov.y);
        hw.y = packh2(ov.z, ov.w);
        *(uint2*)(out_h + (size_t)row * Ec + tid * 4) = hw;
    }
}

// ---------------- fp16 TC GEMM: 128x128x64, 8 warps (2x4), 3-stage cp.async ----------------
enum { EP_PLAIN = 0, EP_HEADS = 1, EP_RES = 2, EP_GELU = 3 };

#define BM 128
#define BN 128
#define BKH 64                       // k-tile in halves
#define LDA2 36                      // As row stride in words (32 data + 4 pad)
#define LDB2 136                     // Bs row stride in words
#define STG_A2 (BM * LDA2)           // 4608 words
#define STG_B2 (32 * LDB2)           // 4352 words
#define STG2   (STG_A2 + STG_B2)     // 8960 words
#define NSTAGE 3
#define TG_SMEM (NSTAGE * STG2 * 4)  // 107520 bytes

template<int EP>
__global__ void __launch_bounds__(256, 2) hgemm(const __half* __restrict__ A,
                                                const uint32_t* __restrict__ Wp,
                                                const float* __restrict__ bias,
                                                const float* __restrict__ res,
                                                float* __restrict__ C,
                                                __half* __restrict__ Ch,
                                                __half* __restrict__ Hq,
                                                __half* __restrict__ Hk,
                                                __half* __restrict__ Hv,
                                                int M, int N, int K) {
    extern __shared__ uint32_t sh[];
    uint32_t smem_u = (uint32_t)__cvta_generic_to_shared(sh);

    int tid  = threadIdx.x;
    int lane = tid & 31;
    int w    = tid >> 5;
    int wm   = (w & 1) * 64;     // 2 warps along M, 64 rows each
    int wn   = (w >> 1) * 32;    // 4 warps along N, 32 cols each
    int row0 = blockIdx.y * BM;
    int col0 = blockIdx.x * BN;

    const __half* Ab = A + (size_t)row0 * K;
    const uint32_t* Wb = Wp + col0;

    auto issue = [&](int kt, int s) {
        uint32_t sa = smem_u + (uint32_t)(s * STG2) * 4u;
        uint32_t sb = sa + (uint32_t)STG_A2 * 4u;
        int k0 = kt * BKH;          // halves
        int k2b = kt * 32;          // half2 rows in Wp
        #pragma unroll
        for (int j = 0; j < 4; j++) {
            int idx = tid + j * 256;
            int r  = idx >> 3, wo = (idx & 7) * 4;               // A: 128 rows x 8 chunks
            cp16(sa + (uint32_t)(r * LDA2 + wo) * 4u, Ab + (size_t)r * K + k0 + wo * 2);
            int kr = idx >> 5, nw = (idx & 31) * 4;              // B: 32 rows x 32 chunks
            cp16(sb + (uint32_t)(kr * LDB2 + nw) * 4u, Wb + (size_t)(k2b + kr) * N + nw);
        }
        CP_COMMIT();
    };

    float acc[4][4][4];
    #pragma unroll
    for (int mi = 0; mi < 4; mi++)
        #pragma unroll
        for (int ni = 0; ni < 4; ni++)
            #pragma unroll
            for (int q = 0; q < 4; q++) acc[mi][ni][q] = 0.f;

    int nk = K / BKH;
    issue(0, 0);
    issue(1, 1);

    int r_ = lane >> 2, c_ = lane & 3;
    int lrow = (lane & 7) + ((lane >> 3) & 1) * 8;   // ldmatrix A row pattern
    int lcol = (lane >> 4) * 4;                      // ldmatrix A col offset (words)

    int st = 0;
    for (int kt = 0; kt < nk; kt++) {
        if (kt + 1 < nk) { CP_WAIT1(); } else { CP_WAIT0(); }
        __syncthreads();
        if (kt + 2 < nk) {
            int s2 = st + 2; if (s2 >= NSTAGE) s2 -= NSTAGE;
            issue(kt + 2, s2);
        }

        uint32_t sa_u = smem_u + (uint32_t)(st * STG2) * 4u;
        const uint32_t* Sb = sh + st * STG2 + STG_A2;

        #pragma unroll
        for (int ks = 0; ks < 4; ks++) {
            int kb2 = ks * 8;
            uint32_t af[4][4], bf[4][2];
            #pragma unroll
            for (int mi = 0; mi < 4; mi++) {
                int row = wm + mi * 16 + lrow;
                ldsm4(af[mi][0], af[mi][1], af[mi][2], af[mi][3],
                      sa_u + (uint32_t)(row * LDA2 + kb2 + lcol) * 4u);
            }
            #pragma unroll
            for (int ni = 0; ni < 4; ni++) {
                int n = wn + ni * 8 + r_;
                bf[ni][0] = Sb[(kb2 + c_) * LDB2 + n];
                bf[ni][1] = Sb[(kb2 + c_ + 4) * LDB2 + n];
            }
            #pragma unroll
            for (int mi = 0; mi < 4; mi++)
                #pragma unroll
                for (int ni = 0; ni < 4; ni++)
                    mma16(acc[mi][ni], af[mi], bf[ni]);
        }
        if (++st == NSTAGE) st = 0;
    }

    // ---- epilogue ----
    int c2 = (lane & 3) * 2;
    #pragma unroll
    for (int mi = 0; mi < 4; mi++) {
        #pragma unroll
        for (int ni = 0; ni < 4; ni++) {
            #pragma unroll
            for (int h = 0; h < 2; h++) {
                int row = row0 + wm + mi * 16 + r_ + h * 8;
                int col = col0 + wn + ni * 8 + c2;
                float v0 = acc[mi][ni][h * 2 + 0] + bias[col];
                float v1 = acc[mi][ni][h * 2 + 1] + bias[col + 1];
                if (EP == EP_GELU) {
                    v0 = 0.5f * v0 * (1.f + erff(v0 * 0.70710678118654752f));
                    v1 = 0.5f * v1 * (1.f + erff(v1 * 0.70710678118654752f));
                    *(uint32_t*)&Ch[(size_t)row * N + col] = packh2(v0, v1);
                } else if (EP == EP_RES) {
                    v0 += res[(size_t)row * N + col];
                    v1 += res[(size_t)row * N + col + 1];
                    *(float2*)&C[(size_t)row * N + col] = make_float2(v0, v1);
                } else if (EP == EP_HEADS) {
                    int mat = col >> 10;           // 0=Q,1=K,2=V (N=3072)
                    int cc  = col & 1023;
                    int bb = row >> 11, ss = row & 2047;
                    int hh = cc >> 6,  dd = cc & 63;
                    if (mat == 0) {                // Q pre-scaled by 0.125*log2e
                        *(uint32_t*)&Hq[(((size_t)(bb * Hc + hh)) * Sc + ss) * Dc + dd] =
                            packh2(v0 * QSCALE, v1 * QSCALE);
                    } else if (mat == 1) {         // K [B,H,S,D]
                        *(uint32_t*)&Hk[(((size_t)(bb * Hc + hh)) * Sc + ss) * Dc + dd] =
                            packh2(v0, v1);
                    } else {                       // V TRANSPOSED [B,H,D,S]
                        size_t base = ((size_t)(bb * Hc + hh)) * Dc;
                        Hv[(base + dd)     * Sc + ss] = __float2half_rn(v0);
                        Hv[(base + dd + 1) * Sc + ss] = __float2half_rn(v1);
                    }
                }
            }
        }
    }
}

// ---------------- fp16 TC flash attention: 64x64 tiles, 128 thr, cp.async + ldmatrix ----------------
#define LDW 36
#define Q_WORDS  (64 * LDW)                     // 2304
#define KV_WORDS (2 * 64 * LDW)                 // K + V per stage: 4608
#define ATTN_SMEM ((Q_WORDS + 2*KV_WORDS + 64*LDW) * 4)   // 55296 bytes

__global__ void __launch_bounds__(128, 3) attn_tc(const __half* __restrict__ Q,
                                                  const __half* __restrict__ K,
                                                  const __half* __restrict__ V,
                                                  __half* __restrict__ ctx) {
    extern __shared__ uint32_t smu[];
    uint32_t smem_u = (uint32_t)__cvta_generic_to_shared(smu);

    int tid = threadIdx.x, lane = tid & 31, w = tid >> 5;
    int r_ = lane >> 2, c_ = lane & 3;
    int qt = (int)gridDim.x - 1 - (int)blockIdx.x;   // heavy tiles first
    int bh = blockIdx.y;
    int q0 = qt * 64;

    const __half* Qb = Q + (size_t)bh * Sc * Dc;
    const __half* Kb = K + (size_t)bh * Sc * Dc;
    const __half* Vb = V + (size_t)bh * Dc * Sc;     // transposed [D][S]

    auto issue_kv = [&](int k0, int s) {
        uint32_t kbase = smem_u + (uint32_t)(Q_WORDS + s * KV_WORDS) * 4u;
        uint32_t vbase = kbase + (uint32_t)(64 * LDW) * 4u;
        #pragma unroll
        for (int it = 0; it < 4; it++) {
            int idx = tid + it * 128;
            int r = idx >> 3, wo = (idx & 7) * 4;
            cp16(kbase + (uint32_t)(r * LDW + wo) * 4u, Kb + (size_t)(k0 + r) * Dc + wo * 2);
            cp16(vbase + (uint32_t)(r * LDW + wo) * 4u, Vb + (size_t)r * Sc + k0 + wo * 2);
        }
        CP_COMMIT();
    };

    {
        #pragma unroll
        for (int it = 0; it < 4; it++) {
            int idx = tid + it * 128;
            int r = idx >> 3, wo = (idx & 7) * 4;
            cp16(smem_u + (uint32_t)(r * LDW + wo) * 4u, Qb + (size_t)(q0 + r) * Dc + wo * 2);
        }
        issue_kv(0, 0);   // commits Q copies too
    }

    float o[8][4];
    #pragma unroll
    for (int nf = 0; nf < 8; nf++)
        #pragma unroll
        for (int q = 0; q < 4; q++) o[nf][q] = 0.f;
    float m0 = -1e30f, m1 = -1e30f, l0 = 0.f, l1 = 0.f;

    uint32_t qf[4][4];
    int w16 = w * 16;
    uint32_t pwbase = smem_u + (uint32_t)(Q_WORDS + 2 * KV_WORDS + w16 * LDW) * 4u;
    uint32_t* pw = smu + Q_WORDS + 2 * KV_WORDS + w16 * LDW;

    int lrow = (lane & 7) + ((lane >> 3) & 1) * 8;   // A-pattern row
    int lcol = (lane >> 4) * 4;                      // A-pattern col offset
    int brow = (lane >> 3) * 8 + (lane & 7);         // B-pattern row

    for (int kt = 0; kt <= qt; kt++) {
        CP_WAIT0();
        __syncthreads();
        if (kt + 1 <= qt) issue_kv((kt + 1) * 64, (kt + 1) & 1);

        if (kt == 0) {    // Q A-frags once (pre-scaled by 0.125*log2e at producer)
            #pragma unroll
            for (int kc = 0; kc < 4; kc++) {
                int row = w16 + lrow;
                ldsm4(qf[kc][0], qf[kc][1], qf[kc][2], qf[kc][3],
                      smem_u + (uint32_t)(row * LDW + kc * 8 + lcol) * 4u);
            }
        }

        uint32_t kbase = smem_u + (uint32_t)(Q_WORDS + (kt & 1) * KV_WORDS) * 4u;
        uint32_t vbase = kbase + (uint32_t)(64 * LDW) * 4u;

        // ---- S(log2 domain) = (Q*0.125*log2e) K^T ----
        float sacc[8][4];
        #pragma unroll
        for (int nf = 0; nf < 8; nf++)
            #pragma unroll
            for (int q = 0; q < 4; q++) sacc[nf][q] = 0.f;
        #pragma unroll
        for (int kc = 0; kc < 4; kc++) {
            int kb = kc * 8;
            uint32_t bf[8][2];
            #pragma unroll
            for (int p = 0; p < 2; p++) {
                int row = p * 32 + brow;
                ldsm4(bf[p*4+0][0], bf[p*4+1][0], bf[p*4+2][0], bf[p*4+3][0],
                      kbase + (uint32_t)(row * LDW + kb) * 4u);
                ldsm4(bf[p*4+0][1], bf[p*4+1][1], bf[p*4+2][1], bf[p*4+3][1],
                      kbase + (uint32_t)(row * LDW + kb + 4) * 4u);
            }
            #pragma unroll
            for (int nf = 0; nf < 8; nf++)
                mma16(sacc[nf], qf[kc], bf[nf]);
        }

        // ---- causal mask on diagonal tile ----
        if (kt == qt) {
            int rr = w16 + r_;
            #pragma unroll
            for (int nf = 0; nf < 8; nf++) {
                int cb = nf * 8 + 2 * c_;
                if (cb     > rr)     sacc[nf][0] = -1e30f;
                if (cb + 1 > rr)     sacc[nf][1] = -1e30f;
                if (cb     > rr + 8) sacc[nf][2] = -1e30f;
                if (cb + 1 > rr + 8) sacc[nf][3] = -1e30f;
            }
        }

        // ---- online softmax (log2 domain: exp2) ----
        float mx0 = -1e30f, mx1 = -1e30f;
        #pragma unroll
        for (int nf = 0; nf < 8; nf++) {
            mx0 = fmaxf(mx0, fmaxf(sacc[nf][0], sacc[nf][1]));
            mx1 = fmaxf(mx1, fmaxf(sacc[nf][2], sacc[nf][3]));
        }
        mx0 = fmaxf(mx0, __shfl_xor_sync(0xffffffffu, mx0, 1));
        mx0 = fmaxf(mx0, __shfl_xor_sync(0xffffffffu, mx0, 2));
        mx1 = fmaxf(mx1, __shfl_xor_sync(0xffffffffu, mx1, 1));
        mx1 = fmaxf(mx1, __shfl_xor_sync(0xffffffffu, mx1, 2));
        float mn0 = fmaxf(m0, mx0), mn1 = fmaxf(m1, mx1);
        float es0 = exp2f(m0 - mn0), es1 = exp2f(m1 - mn1);
        m0 = mn0; m1 = mn1;
        float ls0 = 0.f, ls1 = 0.f;
        #pragma unroll
        for (int nf = 0; nf < 8; nf++) {
            sacc[nf][0] = exp2f(sacc[nf][0] - mn0);
            sacc[nf][1] = exp2f(sacc[nf][1] - mn0);
            sacc[nf][2] = exp2f(sacc[nf][2] - mn1);
            sacc[nf][3] = exp2f(sacc[nf][3] - mn1);
            ls0 += sacc[nf][0] + sacc[nf][1];
            ls1 += sacc[nf][2] + sacc[nf][3];
        }
        ls0 += __shfl_xor_sync(0xffffffffu, ls0, 1);
        ls0 += __shfl_xor_sync(0xffffffffu, ls0, 2);
        ls1 += __shfl_xor_sync(0xffffffffu, ls1, 1);
        ls1 += __shfl_xor_sync(0xffffffffu, ls1, 2);
        l0 = l0 * es0 + ls0;
        l1 = l1 * es1 + ls1;
        #pragma unroll
        for (int nf = 0; nf < 8; nf++) {
            o[nf][0] *= es0; o[nf][1] *= es0;
            o[nf][2] *= es1; o[nf][3] *= es1;
        }

        // ---- P -> warp-private smem as half2 ----
        #pragma unroll
        for (int nf = 0; nf < 8; nf++) {
            int wcol = nf * 4 + c_;
            pw[r_ * LDW + wcol]       = packh2(sacc[nf][0], sacc[nf][1]);
            pw[(r_ + 8) * LDW + wcol] = packh2(sacc[nf][2], sacc[nf][3]);
        }
        __syncwarp();

        // ---- O += P V ----
        #pragma unroll
        for (int kc = 0; kc < 4; kc++) {
            int kb = kc * 8;
            uint32_t af[4];
            ldsm4(af[0], af[1], af[2], af[3],
                  pwbase + (uint32_t)(lrow * LDW + kb + lcol) * 4u);
            uint32_t bf[8][2];
            #pragma unroll
            for (int p = 0; p < 2; p++) {
                int row = p * 32 + brow;
                ldsm4(bf[p*4+0][0], bf[p*4+1][0], bf[p*4+2][0], bf[p*4+3][0],
                      vbase + (uint32_t)(row * LDW + kb) * 4u);
                ldsm4(bf[p*4+0][1], bf[p*4+1][1], bf[p*4+2][1], bf[p*4+3][1],
                      vbase + (uint32_t)(row * LDW + kb + 4) * 4u);
            }
            #pragma unroll
            for (int nf = 0; nf < 8; nf++)
                mma16(o[nf], af, bf[nf]);
        }
        __syncwarp();
    }

    // ---- write ctx [B,S,E] as half ----
    int bb = bh >> 4, hh = bh & 15;
    int row0 = q0 + w16 + r_;
    float il0 = 1.f / l0, il1 = 1.f / l1;
    #pragma unroll
    for (int nf = 0; nf < 8; nf++) {
        int col = hh * 64 + nf * 8 + 2 * c_;
        *(uint32_t*)&ctx[((size_t)bb * Sc + row0) * Ec + col] =
            packh2(o[nf][0] * il0, o[nf][1] * il0);
        *(uint32_t*)&ctx[((size_t)bb * Sc + row0 + 8) * Ec + col] =
            packh2(o[nf][2] * il1, o[nf][3] * il1);
    }
}

// ---------------- launch ----------------
extern "C" void kernel_launch(void* const* d_in, const int* in_sizes, int n_in,
                              void* d_out, int out_size) {
    const float* x    = (const float*)d_in[0];
    const float* Wq   = (const float*)d_in[2];
    const float* bq   = (const float*)d_in[3];
    const float* Wk   = (const float*)d_in[4];
    const float* bk   = (const float*)d_in[5];
    const float* Wv   = (const float*)d_in[6];
    const float* bv   = (const float*)d_in[7];
    const float* Wo   = (const float*)d_in[8];
    const float* bo   = (const float*)d_in[9];
    const float* W1   = (const float*)d_in[10];
    const float* b1   = (const float*)d_in[11];
    const float* W2   = (const float*)d_in[12];
    const float* b2   = (const float*)d_in[13];
    const float* ln1g = (const float*)d_in[14];
    const float* ln1b = (const float*)d_in[15];
    const float* ln2g = (const float*)d_in[16];
    const float* ln2b = (const float*)d_in[17];
    float* out = (float*)d_out;

    __half *n_, *q_, *k_, *v_, *ctx_, *x2h_, *f1_;
    float *res_, *x2_, *bqkv_;
    uint32_t* wp_;
    cudaGetSymbolAddress((void**)&n_,   g_n);
    cudaGetSymbolAddress((void**)&q_,   g_q);
    cudaGetSymbolAddress((void**)&k_,   g_k);
    cudaGetSymbolAddress((void**)&v_,   g_v);
    cudaGetSymbolAddress((void**)&ctx_, g_ctx);
    cudaGetSymbolAddress((void**)&res_, g_res);
    cudaGetSymbolAddress((void**)&x2_,  g_x2);
    cudaGetSymbolAddress((void**)&x2h_, g_x2h);
    cudaGetSymbolAddress((void**)&f1_,  g_f1);
    cudaGetSymbolAddress((void**)&wp_,  g_wp);
    cudaGetSymbolAddress((void**)&bqkv_, g_bqkv);

    cudaFuncSetAttribute(hgemm<EP_HEADS>, cudaFuncAttributeMaxDynamicSharedMemorySize, TG_SMEM);
    cudaFuncSetAttribute(hgemm<EP_RES>,   cudaFuncAttributeMaxDynamicSharedMemorySize, TG_SMEM);
    cudaFuncSetAttribute(hgemm<EP_GELU>,  cudaFuncAttributeMaxDynamicSharedMemorySize, TG_SMEM);
    cudaFuncSetAttribute(attn_tc, cudaFuncAttributeMaxDynamicSharedMemorySize, ATTN_SMEM);

    // 0. convert + pack all weights to fp16 k-interleaved layout (one launch)
    long cblocks = ((WP_TOT + 3072) / 4 + 255) / 256;
    convert_all<<<(int)cblocks, 256>>>(Wq, Wk, Wv, Wo, W1, W2, bq, bk, bv, wp_, bqkv_);

    // 1. LN1 -> half (GEMM A only)
    ln_kernel<false, true><<<Mc, 256>>>(x, ln1g, ln1b, nullptr, n_);

    // 2. fused QKV projection (N=3072) -> Q(scaled)/K half [B,H,S,D], V half [B,H,D,S]
    hgemm<EP_HEADS><<<dim3(3072/BN, Mc/BM), 256, TG_SMEM>>>(n_, wp_ + WP_QKV, bqkv_, nullptr,
                                                            nullptr, nullptr, q_, k_, v_,
                                                            Mc, 3072, Ec);

    // 3. flash attention (fp16 TC, ldmatrix) -> ctx half [B,S,E]
    attn_tc<<<dim3(Sc/64, Bc*Hc), 128, ATTN_SMEM>>>(q_, k_, v_, ctx_);

    // 4. Wo projection + residual with x -> res fp32
    hgemm<EP_RES><<<dim3(Ec/BN, Mc/BM), 256, TG_SMEM>>>(ctx_, wp_ + WP_O, bo, x,
                                                        res_, nullptr, nullptr, nullptr, nullptr,
                                                        Mc, Ec, Ec);

    // 5. LN2 -> x2 fp32 (residual) + x2h half (GEMM A)
    ln_kernel<true, true><<<Mc, 256>>>(res_, ln2g, ln2b, x2_, x2h_);

    // 6. FFN1 + exact GELU -> f1 half
    hgemm<EP_GELU><<<dim3(Fc/BN, Mc/BM), 256, TG_SMEM>>>(x2h_, wp_ + WP_W1, b1, nullptr,
                                                         nullptr, f1_, nullptr, nullptr, nullptr,
                                                         Mc, Fc, Ec);

    // 7. FFN2 + bias + residual(x2) -> out fp32
    hgemm<EP_RES><<<dim3(Ec/BN, Mc/BM), 256, TG_SMEM>>>(f1_, wp_ + WP_W2, b2, x2_,
                                                        out, nullptr, nullptr, nullptr, nullptr,
                                                        Mc, Ec, Fc);
}